// round 17
// baseline (speedup 1.0000x reference)
#include <cuda_runtime.h>
#include <cuda_bf16.h>
#include <math_constants.h>

#define BATCH 1024
#define SEQL  1024
#define NCAT  20
#define NNUM  10
#define EDIM  32
#define ADIM  128
#define HDIM  256
#define TOPK  30
#define ROWS  8

// scratch: fused feature vectors [B, 4E=128]
__device__ float g_fused[BATCH * 128];
// batch-independent folded matrices: M = Wq*Wk^T, N = Wv*Wo  (both [E,E])
__device__ float g_M[EDIM * EDIM];
__device__ float g_N[EDIM * EDIM];

// ---------------------------------------------------------------------------
// Setup: fold Wq/Wk and Wv/Wo into 32x32 matrices. One 1024-thread block.
// ---------------------------------------------------------------------------
__global__ void __launch_bounds__(1024) k_setup(
    const float* __restrict__ Wq, const float* __restrict__ Wk,
    const float* __restrict__ Wv, const float* __restrict__ Wo)
{
    const int t  = threadIdx.x;     // 1024 = 32*32
    const int e  = t >> 5;
    const int e2 = t & 31;
    float m = 0.f, n = 0.f;
    #pragma unroll 8
    for (int a = 0; a < ADIM; a++) {
        m += Wq[e * ADIM + a] * Wk[e2 * ADIM + a];
        n += Wv[e * ADIM + a] * Wo[a * EDIM + e2];
    }
    g_M[e * EDIM + e2] = m;
    g_N[e * EDIM + e2] = n;
}

// ---------------------------------------------------------------------------
// Phase 1 v2: 128-thread CTAs (higher CTAs/SM for latency hiding), folded
// M/N matrices kill the two serialized 128-deep GEMV loops.
// ---------------------------------------------------------------------------
__global__ void __launch_bounds__(128) k_attn(
    const int* __restrict__ cats, const float* __restrict__ nums,
    const int* __restrict__ seqs, const int* __restrict__ tgt_ids,
    const float* __restrict__ cat_emb, const float* __restrict__ seq_emb,
    const float* __restrict__ Wnum, const float* __restrict__ bnum,
    const float* __restrict__ Wpool, const float* __restrict__ bpool,
    const float* __restrict__ bo)
{
    __shared__ float s_tgt[EDIM];
    __shared__ float s_qk[EDIM];
    __shared__ float s_scores[SEQL];
    __shared__ float s_cat[NCAT * EDIM];
    __shared__ float s_red[128];
    __shared__ float s_topw[TOPK];
    __shared__ int   s_toptok[TOPK];
    __shared__ float s_ctx[EDIM];

    const int b    = blockIdx.x;
    const int t    = threadIdx.x;
    const int lane = t & 31;
    const int warp = t >> 5;          // 0..3

    // target embedding + categorical embeddings
    if (t < EDIM) s_tgt[t] = cat_emb[(long)tgt_ids[b] * EDIM + t];
    for (int i = t; i < NCAT * EDIM; i += 128) {
        int c = i >> 5, e = i & 31;
        s_cat[i] = cat_emb[(long)cats[b * NCAT + c] * EDIM + e];
    }
    __syncthreads();

    // qk = M^T tgt  (folded: qk[e2] = sum_e tgt[e] * M[e][e2]) — 32-deep only
    if (t < EDIM) {
        float acc = 0.f;
        #pragma unroll
        for (int e = 0; e < EDIM; e++) acc += s_tgt[e] * g_M[e * EDIM + t];
        s_qk[t] = acc;
    }
    __syncthreads();

    // scores[l] = (qk . seq_emb[seqs[b,l]]) / sqrt(A)
    // 8 lanes/token (float4), 4 tokens concurrent, 16 tokens/iter, 16 iters.
    const float scale = rsqrtf((float)ADIM);
    const int sub = lane & 7;
    const int tg  = lane >> 3;
    const float4 qv4 = *(const float4*)&s_qk[sub * 4];
    const int* srow = seqs + (long)b * SEQL;
    for (int p = warp * 256; p < warp * 256 + 256; p += 16) {
        int tokA = srow[p + tg];
        int tokB = srow[p + 4 + tg];
        int tokC = srow[p + 8 + tg];
        int tokD = srow[p + 12 + tg];
        float4 ea = *(const float4*)(seq_emb + (long)tokA * EDIM + sub * 4);
        float4 eb = *(const float4*)(seq_emb + (long)tokB * EDIM + sub * 4);
        float4 ec = *(const float4*)(seq_emb + (long)tokC * EDIM + sub * 4);
        float4 ed = *(const float4*)(seq_emb + (long)tokD * EDIM + sub * 4);
        float va = ea.x * qv4.x + ea.y * qv4.y + ea.z * qv4.z + ea.w * qv4.w;
        float vb = eb.x * qv4.x + eb.y * qv4.y + eb.z * qv4.z + eb.w * qv4.w;
        float vc = ec.x * qv4.x + ec.y * qv4.y + ec.z * qv4.z + ec.w * qv4.w;
        float vd = ed.x * qv4.x + ed.y * qv4.y + ed.z * qv4.z + ed.w * qv4.w;
        #pragma unroll
        for (int o = 4; o > 0; o >>= 1) {
            va += __shfl_xor_sync(0xffffffffu, va, o);
            vb += __shfl_xor_sync(0xffffffffu, vb, o);
            vc += __shfl_xor_sync(0xffffffffu, vc, o);
            vd += __shfl_xor_sync(0xffffffffu, vd, o);
        }
        if (sub == 0) {
            s_scores[p + tg]      = va * scale;
            s_scores[p + 4 + tg]  = vb * scale;
            s_scores[p + 8 + tg]  = vc * scale;
            s_scores[p + 12 + tg] = vd * scale;
        }
    }
    __syncthreads();

    // ---- top-30 + softmax: single warp, register-resident
    if (warp == 0) {
        float sc[32];
        #pragma unroll
        for (int r = 0; r < 32; r++) sc[r] = s_scores[r * 32 + lane];

        float myval = -CUDART_INF_F;
        int   myidx = 0;

        for (int k = 0; k < TOPK; k++) {
            float bv = sc[0]; int br = 0;
            #pragma unroll
            for (int r = 1; r < 32; r++)
                if (sc[r] > bv) { bv = sc[r]; br = r; }
            int bi = br * 32 + lane;
            #pragma unroll
            for (int o = 16; o > 0; o >>= 1) {
                float ov = __shfl_xor_sync(0xffffffffu, bv, o);
                int   oi = __shfl_xor_sync(0xffffffffu, bi, o);
                if (ov > bv || (ov == bv && oi < bi)) { bv = ov; bi = oi; }
            }
            if (lane == k) { myval = bv; myidx = bi; }
            // static-index knockout keeps sc[] in registers
            const int kr = bi >> 5;
            const int kl = bi & 31;
            #pragma unroll
            for (int r = 0; r < 32; r++)
                sc[r] = (r == kr && lane == kl) ? -CUDART_INF_F : sc[r];
        }

        float m = myval;
        #pragma unroll
        for (int o = 16; o > 0; o >>= 1) m = fmaxf(m, __shfl_xor_sync(0xffffffffu, m, o));
        float ev = (lane < TOPK) ? expf(myval - m) : 0.f;
        float s = ev;
        #pragma unroll
        for (int o = 16; o > 0; o >>= 1) s += __shfl_xor_sync(0xffffffffu, s, o);
        if (lane < TOPK) {
            s_topw[lane]   = ev / s;
            s_toptok[lane] = srow[myidx];
        }
    }
    __syncthreads();

    // ctx[e] = sum_k w_k * seq_emb[tok_k][e]
    if (t < EDIM) {
        float acc = 0.f;
        #pragma unroll
        for (int k = 0; k < TOPK; k++)
            acc += s_topw[k] * seq_emb[(long)s_toptok[k] * EDIM + t];
        s_ctx[t] = acc;
    }
    // cat_pool partials: 4 warps x 160-slice, output dim j = lane
    {
        float cp = 0.f;
        const int j = lane;
        const int i0 = warp * 160;
        for (int i = i0; i < i0 + 160; i++)
            cp += s_cat[i] * Wpool[i * EDIM + j];
        s_red[t] = cp;
    }
    __syncthreads();

    if (t < EDIM) {
        // interest = ctx @ N + bo   (folded: 32-deep)
        float inter = bo[t];
        #pragma unroll
        for (int e = 0; e < EDIM; e++) inter += s_ctx[e] * g_N[e * EDIM + t];
        // cat_pool = sum of 4 partials + bias
        float cp = bpool[t];
        #pragma unroll
        for (int p = 0; p < 4; p++) cp += s_red[p * 32 + t];
        // num_e
        float ne = bnum[t];
        #pragma unroll
        for (int i = 0; i < NNUM; i++) ne += nums[b * NNUM + i] * Wnum[i * EDIM + t];

        float* fo = g_fused + (long)b * 128;
        fo[t]      = s_tgt[t];
        fo[32 + t] = inter;
        fo[64 + t] = cp;
        fo[96 + t] = ne;
    }
}

// ---------------------------------------------------------------------------
// Phase 2 (unchanged from R16 WIN): 1024 threads, split-i partials.
// ---------------------------------------------------------------------------
__global__ void __launch_bounds__(1024, 1) k_mlp(
    const float* __restrict__ Wmlp, const float* __restrict__ bmlp,
    const float* __restrict__ W1a, const float* __restrict__ b1a,
    const float* __restrict__ W2a, const float* __restrict__ b2a,
    const float* __restrict__ Wpa, const float* __restrict__ bpa,
    const float* __restrict__ W1b, const float* __restrict__ b1b,
    const float* __restrict__ W2b, const float* __restrict__ b2b,
    const float* __restrict__ Wpb, const float* __restrict__ bpb,
    const float* __restrict__ Wout, const float* __restrict__ bout,
    float* __restrict__ out)
{
    __shared__ float s_h[ROWS][HDIM];
    __shared__ float s_qd[ROWS][HDIM];
    __shared__ float s_p[4][ROWS][HDIM];

    const int t  = threadIdx.x;
    const int j  = t & 255;
    const int q  = t >> 8;
    const int b0 = blockIdx.x * ROWS;

    float* s_f = (float*)s_qd;
    for (int i = t; i < ROWS * 128; i += 1024)
        s_f[i] = g_fused[(long)b0 * 128 + i];
    __syncthreads();

    {
        float acc[ROWS];
        #pragma unroll
        for (int r = 0; r < ROWS; r++) acc[r] = 0.f;
        const int i0 = q * 32;
        for (int i = i0; i < i0 + 32; i += 4) {
            float w0 = Wmlp[(i + 0) * HDIM + j];
            float w1 = Wmlp[(i + 1) * HDIM + j];
            float w2 = Wmlp[(i + 2) * HDIM + j];
            float w3 = Wmlp[(i + 3) * HDIM + j];
            #pragma unroll
            for (int r = 0; r < ROWS; r++) {
                const float4 f4 = *(const float4*)&s_f[r * 128 + i];
                acc[r] += f4.x * w0 + f4.y * w1 + f4.z * w2 + f4.w * w3;
            }
        }
        #pragma unroll
        for (int r = 0; r < ROWS; r++) s_p[q][r][j] = acc[r];
    }
    __syncthreads();
    {
        const float bm = bmlp[j];
        #pragma unroll
        for (int rr = 0; rr < 2; rr++) {
            const int r = q * 2 + rr;
            float v = bm + s_p[0][r][j] + s_p[1][r][j] + s_p[2][r][j] + s_p[3][r][j];
            s_h[r][j] = fmaxf(v, 0.f);
        }
    }
    __syncthreads();

    #pragma unroll 1
    for (int blk = 0; blk < 2; blk++) {
        const float* W1 = blk ? W1b : W1a;
        const float* B1 = blk ? b1b : b1a;
        const float* W2 = blk ? W2b : W2a;
        const float* B2 = blk ? b2b : b2a;
        const float* Wp = blk ? Wpb : Wpa;
        const float* Bp = blk ? bpb : bpa;
        const int i0 = q * 64;

        {
            float acc[ROWS];
            #pragma unroll
            for (int r = 0; r < ROWS; r++) acc[r] = 0.f;
            for (int i = i0; i < i0 + 64; i += 4) {
                float w0 = W1[(i + 0) * HDIM + j];
                float w1 = W1[(i + 1) * HDIM + j];
                float w2 = W1[(i + 2) * HDIM + j];
                float w3 = W1[(i + 3) * HDIM + j];
                #pragma unroll
                for (int r = 0; r < ROWS; r++) {
                    const float4 h4 = *(const float4*)&s_h[r][i];
                    acc[r] += h4.x * w0 + h4.y * w1 + h4.z * w2 + h4.w * w3;
                }
            }
            #pragma unroll
            for (int r = 0; r < ROWS; r++) s_p[q][r][j] = acc[r];
        }
        __syncthreads();
        {
            const float bb1 = B1[j];
            #pragma unroll
            for (int rr = 0; rr < 2; rr++) {
                const int r = q * 2 + rr;
                s_qd[r][j] = bb1 + s_p[0][r][j] + s_p[1][r][j] + s_p[2][r][j] + s_p[3][r][j];
            }
        }
        __syncthreads();

        {
            float acc[ROWS];
            #pragma unroll
            for (int r = 0; r < ROWS; r++) acc[r] = 0.f;
            for (int i = i0; i < i0 + 64; i += 4) {
                float w0 = W2[(i + 0) * HDIM + j];
                float w1 = W2[(i + 1) * HDIM + j];
                float w2 = W2[(i + 2) * HDIM + j];
                float w3 = W2[(i + 3) * HDIM + j];
                #pragma unroll
                for (int r = 0; r < ROWS; r++) {
                    const float4 h4 = *(const float4*)&s_h[r][i];
                    acc[r] += h4.x * w0 + h4.y * w1 + h4.z * w2 + h4.w * w3;
                }
            }
            #pragma unroll
            for (int r = 0; r < ROWS; r++) s_p[q][r][j] = acc[r];
        }
        __syncthreads();
        {
            const float bb2 = B2[j];
            #pragma unroll
            for (int rr = 0; rr < 2; rr++) {
                const int r = q * 2 + rr;
                float t2v = bb2 + s_p[0][r][j] + s_p[1][r][j] + s_p[2][r][j] + s_p[3][r][j];
                s_qd[r][j] = s_qd[r][j] * t2v;
            }
        }
        __syncthreads();

        {
            float acc[ROWS];
            #pragma unroll
            for (int r = 0; r < ROWS; r++) acc[r] = 0.f;
            for (int i = i0; i < i0 + 64; i += 4) {
                float w0 = Wp[(i + 0) * HDIM + j];
                float w1 = Wp[(i + 1) * HDIM + j];
                float w2 = Wp[(i + 2) * HDIM + j];
                float w3 = Wp[(i + 3) * HDIM + j];
                #pragma unroll
                for (int r = 0; r < ROWS; r++) {
                    const float4 q4 = *(const float4*)&s_qd[r][i];
                    acc[r] += q4.x * w0 + q4.y * w1 + q4.z * w2 + q4.w * w3;
                }
            }
            #pragma unroll
            for (int r = 0; r < ROWS; r++) s_p[q][r][j] = acc[r];
        }
        __syncthreads();
        {
            const float bp_ = Bp[j];
            #pragma unroll
            for (int rr = 0; rr < 2; rr++) {
                const int r = q * 2 + rr;
                s_h[r][j] += bp_ + s_p[0][r][j] + s_p[1][r][j] + s_p[2][r][j] + s_p[3][r][j];
            }
        }
        __syncthreads();
    }

    {
        const int w    = t >> 5;
        const int lane = t & 31;
        const int r    = w >> 2;
        const int jb   = (w & 3) * 64;
        float sum = s_h[r][jb + lane]      * Wout[jb + lane]
                  + s_h[r][jb + 32 + lane] * Wout[jb + 32 + lane];
        #pragma unroll
        for (int o = 16; o > 0; o >>= 1)
            sum += __shfl_xor_sync(0xffffffffu, sum, o);
        float* s_hd = (float*)s_p;
        if (lane == 0) s_hd[w] = sum;
        __syncthreads();
        if (t < ROWS)
            out[b0 + t] = bout[0] + s_hd[t * 4] + s_hd[t * 4 + 1]
                        + s_hd[t * 4 + 2] + s_hd[t * 4 + 3];
    }
}

extern "C" void kernel_launch(void* const* d_in, const int* in_sizes, int n_in,
                              void* d_out, int out_size)
{
    const int*   cats    = (const int*)d_in[0];
    const float* nums    = (const float*)d_in[1];
    const int*   seqs    = (const int*)d_in[2];
    const int*   tgt_ids = (const int*)d_in[3];
    const float* cat_emb = (const float*)d_in[4];
    const float* seq_emb = (const float*)d_in[5];
    const float* Wnum    = (const float*)d_in[6];
    const float* bnum    = (const float*)d_in[7];
    const float* Wq      = (const float*)d_in[8];
    const float* Wk      = (const float*)d_in[9];
    const float* Wv      = (const float*)d_in[10];
    const float* Wo      = (const float*)d_in[11];
    const float* bo      = (const float*)d_in[12];
    const float* Wpool   = (const float*)d_in[13];
    const float* bpool   = (const float*)d_in[14];
    const float* Wmlp    = (const float*)d_in[15];
    const float* bmlp    = (const float*)d_in[16];
    const float* q1_W1   = (const float*)d_in[17];
    const float* q1_b1   = (const float*)d_in[18];
    const float* q1_W2   = (const float*)d_in[19];
    const float* q1_b2   = (const float*)d_in[20];
    const float* q1_Wp   = (const float*)d_in[21];
    const float* q1_bp   = (const float*)d_in[22];
    const float* q2_W1   = (const float*)d_in[23];
    const float* q2_b1   = (const float*)d_in[24];
    const float* q2_W2   = (const float*)d_in[25];
    const float* q2_b2   = (const float*)d_in[26];
    const float* q2_Wp   = (const float*)d_in[27];
    const float* q2_bp   = (const float*)d_in[28];
    const float* Wout    = (const float*)d_in[29];
    const float* bout    = (const float*)d_in[30];
    float* out = (float*)d_out;

    k_setup<<<1, 1024>>>(Wq, Wk, Wv, Wo);
    k_attn<<<BATCH, 128>>>(cats, nums, seqs, tgt_ids, cat_emb, seq_emb,
                           Wnum, bnum, Wpool, bpool, bo);
    k_mlp<<<BATCH / ROWS, 1024>>>(Wmlp, bmlp,
                                  q1_W1, q1_b1, q1_W2, q1_b2, q1_Wp, q1_bp,
                                  q2_W1, q2_b1, q2_W2, q2_b2, q2_Wp, q2_bp,
                                  Wout, bout, out);
}